// round 12
// baseline (speedup 1.0000x reference)
#include <cuda_runtime.h>
#include <cstdint>
#include <cstddef>

#define TSTEPS 512
#define BATCH  128

// 192MB scratch for the input projection (static device array: allowed).
__device__ float g_Gx[(size_t)BATCH * TSTEPS * 768];

// ---- f32x2 helpers ----
typedef unsigned long long ull;
__device__ __forceinline__ ull pack2(float x, float y) {
    ull u; asm("mov.b64 %0, {%1,%2};" : "=l"(u) : "f"(x), "f"(y)); return u;
}
__device__ __forceinline__ void unpack2(ull u, float& x, float& y) {
    asm("mov.b64 {%0,%1}, %2;" : "=f"(x), "=f"(y) : "l"(u));
}
__device__ __forceinline__ void fma2(ull& d, ull a, ull b) {
    asm("fma.rn.f32x2 %0, %1, %2, %0;" : "+l"(d) : "l"(a), "l"(b));
}

// ---- cluster / mbarrier helpers ----
__device__ __forceinline__ uint32_t smem_u32(const void* p) {
    uint32_t a;
    asm("{ .reg .u64 t; cvta.to.shared.u64 t, %1; cvt.u32.u64 %0, t; }" : "=r"(a) : "l"(p));
    return a;
}
__device__ __forceinline__ uint32_t mapa_rank(uint32_t addr, uint32_t rank) {
    uint32_t r; asm("mapa.shared::cluster.u32 %0, %1, %2;" : "=r"(r) : "r"(addr), "r"(rank));
    return r;
}
__device__ __forceinline__ void st_cluster_u64(uint32_t addr, ull v) {
    asm volatile("st.shared::cluster.b64 [%0], %1;" :: "r"(addr), "l"(v));
}
__device__ __forceinline__ void cluster_sync() {
    asm volatile("barrier.cluster.arrive.aligned;" ::: "memory");
    asm volatile("barrier.cluster.wait.aligned;" ::: "memory");
}
__device__ __forceinline__ uint32_t cluster_rank() {
    uint32_t r; asm("mov.u32 %0, %%cluster_ctarank;" : "=r"(r)); return r;
}
__device__ __forceinline__ void mbar_init(uint32_t addr, uint32_t count) {
    asm volatile("mbarrier.init.shared.b64 [%0], %1;" :: "r"(addr), "r"(count) : "memory");
}
__device__ __forceinline__ void mbar_arrive_remote(uint32_t addr) {
    asm volatile("mbarrier.arrive.release.cluster.shared::cluster.b64 _, [%0];"
                 :: "r"(addr) : "memory");
}
__device__ __forceinline__ void mbar_wait(uint32_t addr, uint32_t parity) {
    uint32_t done = 0;
    do {
        asm volatile("{\n\t.reg .pred p;\n\t"
            "mbarrier.try_wait.parity.acquire.cluster.shared::cta.b64 p, [%1], %2, 0x989680;\n\t"
            "selp.b32 %0, 1, 0, p;\n\t}"
            : "=r"(done) : "r"(addr), "r"(parity) : "memory");
    } while (!done);
}

// fast activations
__device__ __forceinline__ float fast_sigmoid(float x) {
    return __fdividef(1.0f, 1.0f + __expf(-x));
}
__device__ __forceinline__ float fast_tanh(float x) {
    return 2.0f * __fdividef(1.0f, 1.0f + __expf(-2.0f * x)) - 1.0f;
}

// butterfly reduce a (lo,hi) pair over the kg dimension (lane bits 2,3,4)
__device__ __forceinline__ void bfly_kg(float& lo, float& hi) {
    lo += __shfl_xor_sync(0xffffffffu, lo, 4);
    hi += __shfl_xor_sync(0xffffffffu, hi, 4);
    lo += __shfl_xor_sync(0xffffffffu, lo, 8);
    hi += __shfl_xor_sync(0xffffffffu, hi, 8);
    lo += __shfl_xor_sync(0xffffffffu, lo, 16);
    hi += __shfl_xor_sync(0xffffffffu, hi, 16);
}

// ============================================================================
// Stage 1: Gx[m][gate*256+n] = x[m] @ W[:256] + b.  BM=128 BN=64 BK=32.
// ============================================================================
__global__ __launch_bounds__(256) void proj_kernel(
    const float* __restrict__ x,
    const float* __restrict__ Wr, const float* __restrict__ br,
    const float* __restrict__ Wz, const float* __restrict__ bz,
    const float* __restrict__ Wc, const float* __restrict__ bc)
{
    const int mTile = blockIdx.x, nTile = blockIdx.y;
    const int gate = nTile >> 2, nGateBase = (nTile & 3) * 64;
    const float* W    = (gate == 0) ? Wr : ((gate == 1) ? Wz : Wc);
    const float* bias = (gate == 0) ? br : ((gate == 1) ? bz : bc);

    __shared__ float As[32][132];   // [k][m]
    __shared__ float Ws[32][64];    // [k][n]

    const int tid = threadIdx.x;
    const int tx = tid & 15, ty = tid >> 4;
    const int mBase = mTile * 128;

    ull acc[4][4];
    #pragma unroll
    for (int i = 0; i < 4; i++)
        #pragma unroll
        for (int jj = 0; jj < 4; jj++) acc[i][jj] = 0ull;

    float bv[4];
    #pragma unroll
    for (int jj = 0; jj < 4; jj++) bv[jj] = bias[nGateBase + tx * 4 + jj];

    for (int k0 = 0; k0 < 256; k0 += 32) {
        __syncthreads();
        #pragma unroll
        for (int q = 0; q < 4; q++) {
            int idx = tid + q * 256, row = idx >> 3, c4 = idx & 7;
            float4 v = *reinterpret_cast<const float4*>(
                &x[(size_t)(mBase + row) * 256 + k0 + c4 * 4]);
            As[c4 * 4 + 0][row] = v.x; As[c4 * 4 + 1][row] = v.y;
            As[c4 * 4 + 2][row] = v.z; As[c4 * 4 + 3][row] = v.w;
        }
        #pragma unroll
        for (int q = 0; q < 2; q++) {
            int s = tid + q * 256;
            int k = s >> 4, n4 = (s & 15) * 4;
            *reinterpret_cast<float4*>(&Ws[k][n4]) =
                *reinterpret_cast<const float4*>(&W[(size_t)(k0 + k) * 256 + nGateBase + n4]);
        }
        __syncthreads();

        #pragma unroll
        for (int k = 0; k < 32; k++) {
            const ull* ap = reinterpret_cast<const ull*>(&As[k][ty * 8]);
            ull a0 = ap[0], a1 = ap[1], a2 = ap[2], a3 = ap[3];
            #pragma unroll
            for (int jj = 0; jj < 4; jj++) {
                float w = Ws[k][tx * 4 + jj];
                ull w2 = pack2(w, w);
                fma2(acc[0][jj], a0, w2); fma2(acc[1][jj], a1, w2);
                fma2(acc[2][jj], a2, w2); fma2(acc[3][jj], a3, w2);
            }
        }
    }

    const int nOut = gate * 256 + nGateBase + tx * 4;
    #pragma unroll
    for (int rp = 0; rp < 4; rp++) {
        float r0[4], r1[4];
        #pragma unroll
        for (int jj = 0; jj < 4; jj++) {
            unpack2(acc[rp][jj], r0[jj], r1[jj]);
            r0[jj] += bv[jj]; r1[jj] += bv[jj];
        }
        int m0 = mBase + ty * 8 + rp * 2;
        *reinterpret_cast<float4*>(&g_Gx[(size_t)m0 * 768 + nOut]) =
            make_float4(r0[0], r0[1], r0[2], r0[3]);
        *reinterpret_cast<float4*>(&g_Gx[(size_t)(m0 + 1) * 768 + nOut]) =
            make_float4(r1[0], r1[1], r1[2], r1[3]);
    }
}

// ============================================================================
// Stage 2: recurrence. 32 clusters x 8 CTAs, 4 rows/cluster split into two
// row groups A={0,1}, B={2,3}. Intra-warp split-K (shfl butterfly). Each
// group's DSMEM exchange is covered by the other group's GEMM; sync via 4
// DSMEM mbarriers (count=8, elected release-arrives after __syncthreads).
// ============================================================================
struct __align__(16) RecSmem {
    float wc4[32][8][8][4];    // Wc h-part [kk][c>>2][kg][c&3]          32KB
    ull   hA[2][264];          // h rows {0,1} packed, skewed, [buf]
    ull   hB[2][264];          // h rows {2,3}
    ull   rhA[264];            // r*h rows {0,1}
    ull   rhB[264];
    unsigned long long mbar[4];  // 0=hA, 1=hB, 2=rhA, 3=rhB (count=8)
};

__global__ __launch_bounds__(256, 2) __cluster_dims__(8, 1, 1)
void rec_kernel(const float* __restrict__ h0,
                const float* __restrict__ Wr,
                const float* __restrict__ Wz,
                const float* __restrict__ Wc,
                float* __restrict__ out)
{
    extern __shared__ char smem_raw[];
    RecSmem& S = *reinterpret_cast<RecSmem*>(smem_raw);

    const int tid = threadIdx.x;
    const int warp = tid >> 5, lane = tid & 31;
    const int j = (int)cluster_rank();       // 0..7
    const int b0 = (blockIdx.x >> 3) * 4;    // first batch row of cluster

    // roles
    const int c_local = warp * 4 + (lane & 3);   // output col within CTA
    const int kg = lane >> 2;                    // split-K group, 0..7
    const int base33 = 33 * kg;                  // skewed row base (kb=32kg)
    const bool pusher = (lane < 16);
    const int pg = (lane >> 2) & 3;              // peer group (pushers): 0..3
    const int k_glob = j * 32 + c_local;
    const int sk_own = k_glob + j;               // skewed row of own col

    // ---- register weights for r and z gates (1 col x 32 k each) ----
    float w1r[32], w1z[32];
    {
        const int kb = 32 * kg;
        #pragma unroll
        for (int kk = 0; kk < 32; kk++) {
            w1r[kk] = Wr[(size_t)(256 + kb + kk) * 256 + k_glob];
            w1z[kk] = Wz[(size_t)(256 + kb + kk) * 256 + k_glob];
        }
    }

    // ---- SMEM init: Wc tile, h state (buffer 0), mbarriers ----
    for (int idx = tid; idx < 8192; idx += 256) {
        int k = idx >> 5, c = idx & 31;
        S.wc4[k & 31][c >> 2][k >> 5][c & 3] =
            Wc[(size_t)(256 + k) * 256 + j * 32 + c];
    }
    {
        int k = tid;   // 256 threads = 256 k values
        int sk = k + (k >> 5);
        S.hA[0][sk] = pack2(h0[(size_t)b0 * 256 + k],       h0[(size_t)(b0 + 1) * 256 + k]);
        S.hB[0][sk] = pack2(h0[(size_t)(b0 + 2) * 256 + k], h0[(size_t)(b0 + 3) * 256 + k]);
    }
    if (tid == 0) {
        #pragma unroll
        for (int c = 0; c < 4; c++) mbar_init(smem_u32(&S.mbar[c]), 8);
    }
    __syncthreads();
    cluster_sync();   // peers' init visible before any remote op

    // ---- peer DSMEM addressing (each pusher serves peers 2pg, 2pg+1) ----
    const uint32_t base = smem_u32(&S);
    const uint32_t peerX = mapa_rank(base, (uint32_t)(2 * pg));
    const uint32_t peerY = mapa_rank(base, (uint32_t)(2 * pg + 1));
    const uint32_t o_hA[2]  = { (uint32_t)(smem_u32(&S.hA[0][0]) - base) + (uint32_t)(sk_own * 8),
                                (uint32_t)(smem_u32(&S.hA[1][0]) - base) + (uint32_t)(sk_own * 8) };
    const uint32_t o_hB[2]  = { (uint32_t)(smem_u32(&S.hB[0][0]) - base) + (uint32_t)(sk_own * 8),
                                (uint32_t)(smem_u32(&S.hB[1][0]) - base) + (uint32_t)(sk_own * 8) };
    const uint32_t o_rhA    = (uint32_t)(smem_u32(&S.rhA[0]) - base) + (uint32_t)(sk_own * 8);
    const uint32_t o_rhB    = (uint32_t)(smem_u32(&S.rhB[0]) - base) + (uint32_t)(sk_own * 8);
    const uint32_t bar_hA  = smem_u32(&S.mbar[0]);
    const uint32_t bar_hB  = smem_u32(&S.mbar[1]);
    const uint32_t bar_rhA = smem_u32(&S.mbar[2]);
    const uint32_t bar_rhB = smem_u32(&S.mbar[3]);
    // elected arriving threads: tid 0..7 -> peer tid
    uint32_t rem_hA = 0, rem_hB = 0, rem_rhA = 0, rem_rhB = 0;
    if (tid < 8) {
        rem_hA  = mapa_rank(bar_hA,  (uint32_t)tid);
        rem_hB  = mapa_rank(bar_hB,  (uint32_t)tid);
        rem_rhA = mapa_rank(bar_rhA, (uint32_t)tid);
        rem_rhB = mapa_rank(bar_rhB, (uint32_t)tid);
    }

    // ---- Gx bases for pusher lanes ----
    const size_t bA0 = (size_t)b0 * TSTEPS * 768 + k_glob;
    const size_t bA1 = bA0 + (size_t)TSTEPS * 768;
    const size_t bB0 = bA0 + (size_t)2 * TSTEPS * 768;
    const size_t bB1 = bA0 + (size_t)3 * TSTEPS * 768;

    // prologue: gR for step 0
    float gRA0 = 0.f, gRA1 = 0.f, gRB0 = 0.f, gRB1 = 0.f;
    if (pusher) {
        gRA0 = g_Gx[bA0]; gRA1 = g_Gx[bA1];
        gRB0 = g_Gx[bB0]; gRB1 = g_Gx[bB1];
    }

    #pragma unroll 1
    for (int t = 0; t < TSTEPS; t++) {
        const int buf = t & 1;
        const uint32_t p_h  = (uint32_t)((t - 1) & 1);
        const uint32_t p_rh = (uint32_t)(t & 1);

        // gZ/gC loads for this step (latency hidden under early GEMMs)
        float gZA0 = 0.f, gZA1 = 0.f, gCA0 = 0.f, gCA1 = 0.f;
        float gZB0 = 0.f, gZB1 = 0.f, gCB0 = 0.f, gCB1 = 0.f;
        if (pusher) {
            const size_t to = (size_t)t * 768;
            gZA0 = g_Gx[bA0 + to + 256]; gZA1 = g_Gx[bA1 + to + 256];
            gCA0 = g_Gx[bA0 + to + 512]; gCA1 = g_Gx[bA1 + to + 512];
            gZB0 = g_Gx[bB0 + to + 256]; gZB1 = g_Gx[bB1 + to + 256];
            gCB0 = g_Gx[bB0 + to + 512]; gCB1 = g_Gx[bB1 + to + 512];
        }

        // ======== group A: reset gate ========
        if (t > 0) mbar_wait(bar_hA, p_h);
        {
            ull a = 0;
            #pragma unroll
            for (int kk = 0; kk < 32; kk++)
                fma2(a, S.hA[buf][base33 + kk], pack2(w1r[kk], w1r[kk]));
            float lo, hi; unpack2(a, lo, hi);
            bfly_kg(lo, hi);
            if (pusher) {
                float v0 = fast_sigmoid(lo + gRA0), v1 = fast_sigmoid(hi + gRA1);
                float ha, hb; unpack2(S.hA[buf][sk_own], ha, hb);
                ull rh2 = pack2(v0 * ha, v1 * hb);
                st_cluster_u64(peerX + o_rhA, rh2);
                st_cluster_u64(peerY + o_rhA, rh2);
            }
        }
        __syncthreads();
        if (tid < 8) mbar_arrive_remote(rem_rhA);

        // ======== group B: reset gate (covers hB wait with A work above) ====
        if (t > 0) mbar_wait(bar_hB, p_h);
        {
            ull a = 0;
            #pragma unroll
            for (int kk = 0; kk < 32; kk++)
                fma2(a, S.hB[buf][base33 + kk], pack2(w1r[kk], w1r[kk]));
            float lo, hi; unpack2(a, lo, hi);
            bfly_kg(lo, hi);
            if (pusher) {
                float v0 = fast_sigmoid(lo + gRB0), v1 = fast_sigmoid(hi + gRB1);
                float ha, hb; unpack2(S.hB[buf][sk_own], ha, hb);
                ull rh2 = pack2(v0 * ha, v1 * hb);
                st_cluster_u64(peerX + o_rhB, rh2);
                st_cluster_u64(peerY + o_rhB, rh2);
            }
        }
        __syncthreads();
        if (tid < 8) mbar_arrive_remote(rem_rhB);

        // ======== update gates (cover for the rh exchanges) ========
        float zA0 = 0.f, zA1 = 0.f, zB0 = 0.f, zB1 = 0.f;
        {
            ull a = 0;
            #pragma unroll
            for (int kk = 0; kk < 32; kk++)
                fma2(a, S.hA[buf][base33 + kk], pack2(w1z[kk], w1z[kk]));
            float lo, hi; unpack2(a, lo, hi);
            bfly_kg(lo, hi);
            if (pusher) { zA0 = fast_sigmoid(lo + gZA0); zA1 = fast_sigmoid(hi + gZA1); }
        }
        {
            ull a = 0;
            #pragma unroll
            for (int kk = 0; kk < 32; kk++)
                fma2(a, S.hB[buf][base33 + kk], pack2(w1z[kk], w1z[kk]));
            float lo, hi; unpack2(a, lo, hi);
            bfly_kg(lo, hi);
            if (pusher) { zB0 = fast_sigmoid(lo + gZB0); zB1 = fast_sigmoid(hi + gZB1); }
        }

        // prefetch gR(t+1): in flight across GEMM_c chunks
        float gRnA0 = gRA0, gRnA1 = gRA1, gRnB0 = gRB0, gRnB1 = gRB1;
        if (pusher) {
            const size_t tn = (size_t)((t + 1 < TSTEPS) ? t + 1 : t) * 768;
            gRnA0 = g_Gx[bA0 + tn]; gRnA1 = g_Gx[bA1 + tn];
            gRnB0 = g_Gx[bB0 + tn]; gRnB1 = g_Gx[bB1 + tn];
        }

        // ======== group A: candidate + h update ========
        mbar_wait(bar_rhA, p_rh);
        float hnA0 = 0.f, hnA1 = 0.f;
        {
            ull a = 0;
            #pragma unroll
            for (int kk = 0; kk < 32; kk++) {
                float w = S.wc4[kk][c_local >> 2][kg][c_local & 3];
                fma2(a, S.rhA[base33 + kk], pack2(w, w));
            }
            float lo, hi; unpack2(a, lo, hi);
            bfly_kg(lo, hi);
            if (pusher) {
                float c0 = fast_tanh(lo + gCA0), c1 = fast_tanh(hi + gCA1);
                float ha, hb; unpack2(S.hA[buf][sk_own], ha, hb);
                hnA0 = ha + zA0 * (c0 - ha);
                hnA1 = hb + zA1 * (c1 - hb);
                ull hn2 = pack2(hnA0, hnA1);
                st_cluster_u64(peerX + o_hA[buf ^ 1], hn2);
                st_cluster_u64(peerY + o_hA[buf ^ 1], hn2);
            }
        }
        __syncthreads();
        if (tid < 8) mbar_arrive_remote(rem_hA);

        // ======== group B: candidate + h update (covers hA exchange) ========
        mbar_wait(bar_rhB, p_rh);
        float hnB0 = 0.f, hnB1 = 0.f;
        {
            ull a = 0;
            #pragma unroll
            for (int kk = 0; kk < 32; kk++) {
                float w = S.wc4[kk][c_local >> 2][kg][c_local & 3];
                fma2(a, S.rhB[base33 + kk], pack2(w, w));
            }
            float lo, hi; unpack2(a, lo, hi);
            bfly_kg(lo, hi);
            if (pusher) {
                float c0 = fast_tanh(lo + gCB0), c1 = fast_tanh(hi + gCB1);
                float ha, hb; unpack2(S.hB[buf][sk_own], ha, hb);
                hnB0 = ha + zB0 * (c0 - ha);
                hnB1 = hb + zB1 * (c1 - hb);
                ull hn2 = pack2(hnB0, hnB1);
                st_cluster_u64(peerX + o_hB[buf ^ 1], hn2);
                st_cluster_u64(peerY + o_hB[buf ^ 1], hn2);
            }
        }
        __syncthreads();
        if (tid < 8) mbar_arrive_remote(rem_hB);

        // output stores after the arrives (no consumer until kernel end)
        if (pusher && pg == 0) {
            out[((size_t)(b0 + 0) * TSTEPS + t) * 256 + k_glob] = hnA0;
            out[((size_t)(b0 + 1) * TSTEPS + t) * 256 + k_glob] = hnA1;
            out[((size_t)(b0 + 2) * TSTEPS + t) * 256 + k_glob] = hnB0;
            out[((size_t)(b0 + 3) * TSTEPS + t) * 256 + k_glob] = hnB1;
        }

        gRA0 = gRnA0; gRA1 = gRnA1; gRB0 = gRnB0; gRB1 = gRnB1;
    }

    // drain final h phases; full cluster sync before exit
    mbar_wait(bar_hA, (uint32_t)((TSTEPS - 1) & 1));
    mbar_wait(bar_hB, (uint32_t)((TSTEPS - 1) & 1));
    cluster_sync();
}

extern "C" void kernel_launch(void* const* d_in, const int* in_sizes, int n_in,
                              void* d_out, int out_size) {
    const float* x  = (const float*)d_in[0];
    const float* h0 = (const float*)d_in[1];
    const float* Wr = (const float*)d_in[2];
    const float* br = (const float*)d_in[3];
    const float* Wz = (const float*)d_in[4];
    const float* bz = (const float*)d_in[5];
    const float* Wc = (const float*)d_in[6];
    const float* bc = (const float*)d_in[7];
    float* out = (float*)d_out;

    cudaFuncSetAttribute(rec_kernel, cudaFuncAttributeMaxDynamicSharedMemorySize,
                         (int)sizeof(RecSmem));

    proj_kernel<<<dim3(512, 12), 256>>>(x, Wr, br, Wz, bz, Wc, bc);
    rec_kernel<<<256, 256, sizeof(RecSmem)>>>(h0, Wr, Wz, Wc, out);
}

// round 13
// speedup vs baseline: 1.0969x; 1.0969x over previous
#include <cuda_runtime.h>
#include <cstdint>
#include <cstddef>

#define TSTEPS 512
#define BATCH  128

// 192MB scratch for the input projection (static device array: allowed).
__device__ float g_Gx[(size_t)BATCH * TSTEPS * 768];

// ---- f32x2 helpers ----
typedef unsigned long long ull;
__device__ __forceinline__ ull pack2(float x, float y) {
    ull u; asm("mov.b64 %0, {%1,%2};" : "=l"(u) : "f"(x), "f"(y)); return u;
}
__device__ __forceinline__ void unpack2(ull u, float& x, float& y) {
    asm("mov.b64 {%0,%1}, %2;" : "=f"(x), "=f"(y) : "l"(u));
}
__device__ __forceinline__ void fma2(ull& d, ull a, ull b) {
    asm("fma.rn.f32x2 %0, %1, %2, %0;" : "+l"(d) : "l"(a), "l"(b));
}

// ---- cluster helpers ----
__device__ __forceinline__ uint32_t smem_u32(const void* p) {
    uint32_t a;
    asm("{ .reg .u64 t; cvta.to.shared.u64 t, %1; cvt.u32.u64 %0, t; }" : "=r"(a) : "l"(p));
    return a;
}
__device__ __forceinline__ uint32_t mapa_rank(uint32_t addr, uint32_t rank) {
    uint32_t r; asm("mapa.shared::cluster.u32 %0, %1, %2;" : "=r"(r) : "r"(addr), "r"(rank));
    return r;
}
__device__ __forceinline__ void st_cluster_u64(uint32_t addr, ull v) {
    asm volatile("st.shared::cluster.b64 [%0], %1;" :: "r"(addr), "l"(v));
}
__device__ __forceinline__ void cluster_arrive() {
    asm volatile("barrier.cluster.arrive.aligned;" ::: "memory");
}
__device__ __forceinline__ void cluster_wait() {
    asm volatile("barrier.cluster.wait.aligned;" ::: "memory");
}
__device__ __forceinline__ void cluster_sync() {
    cluster_arrive(); cluster_wait();
}
__device__ __forceinline__ uint32_t cluster_rank() {
    uint32_t r; asm("mov.u32 %0, %%cluster_ctarank;" : "=r"(r)); return r;
}

// fast activations
__device__ __forceinline__ float fast_sigmoid(float x) {
    return __fdividef(1.0f, 1.0f + __expf(-x));
}
__device__ __forceinline__ float fast_tanh(float x) {
    return 2.0f * __fdividef(1.0f, 1.0f + __expf(-2.0f * x)) - 1.0f;
}

// butterfly reduce a (lo,hi) pair over the kg dimension (lane bits 2,3,4)
__device__ __forceinline__ void bfly_kg(float& lo, float& hi) {
    lo += __shfl_xor_sync(0xffffffffu, lo, 4);
    hi += __shfl_xor_sync(0xffffffffu, hi, 4);
    lo += __shfl_xor_sync(0xffffffffu, lo, 8);
    hi += __shfl_xor_sync(0xffffffffu, hi, 8);
    lo += __shfl_xor_sync(0xffffffffu, lo, 16);
    hi += __shfl_xor_sync(0xffffffffu, hi, 16);
}

// ============================================================================
// Stage 1: Gx[m][gate*256+n] = x[m] @ W[:256] + b.  BM=128 BN=64 BK=32.
// Two-stage software pipeline: double-buffered SMEM tiles, ONE sync per
// k-chunk, next tile's LDGs in flight during compute.
// ============================================================================
#define PROJ_SMEM_FLOATS (2 * (32 * 132 + 32 * 64))

__global__ __launch_bounds__(256) void proj_kernel(
    const float* __restrict__ x,
    const float* __restrict__ Wr, const float* __restrict__ br,
    const float* __restrict__ Wz, const float* __restrict__ bz,
    const float* __restrict__ Wc, const float* __restrict__ bc)
{
    extern __shared__ float psm[];
    // layout: As[2][32][132], Ws[2][32][64]
    float (*As)[32][132] = reinterpret_cast<float (*)[32][132]>(psm);
    float (*Ws)[32][64]  = reinterpret_cast<float (*)[32][64]>(psm + 2 * 32 * 132);

    const int mTile = blockIdx.x, nTile = blockIdx.y;
    const int gate = nTile >> 2, nGateBase = (nTile & 3) * 64;
    const float* W    = (gate == 0) ? Wr : ((gate == 1) ? Wz : Wc);
    const float* bias = (gate == 0) ? br : ((gate == 1) ? bz : bc);

    const int tid = threadIdx.x;
    const int tx = tid & 15, ty = tid >> 4;
    const int mBase = mTile * 128;

    // per-thread load indices (fixed across chunks)
    const int a_row[4] = { (tid + 0) >> 3, (tid + 256) >> 3,
                           (tid + 512) >> 3, (tid + 768) >> 3 };
    const int a_c4[4]  = { (tid + 0) & 7, (tid + 256) & 7,
                           (tid + 512) & 7, (tid + 768) & 7 };
    const int w_k[2]   = { (tid + 0) >> 4, (tid + 256) >> 4 };
    const int w_n4[2]  = { ((tid + 0) & 15) * 4, ((tid + 256) & 15) * 4 };

    float4 aReg[4], wReg[2];

    // --- prologue: load chunk 0 into regs, store to buffer 0 ---
    #pragma unroll
    for (int q = 0; q < 4; q++)
        aReg[q] = *reinterpret_cast<const float4*>(
            &x[(size_t)(mBase + a_row[q]) * 256 + a_c4[q] * 4]);
    #pragma unroll
    for (int q = 0; q < 2; q++)
        wReg[q] = *reinterpret_cast<const float4*>(
            &W[(size_t)w_k[q] * 256 + nGateBase + w_n4[q]]);
    #pragma unroll
    for (int q = 0; q < 4; q++) {
        As[0][a_c4[q] * 4 + 0][a_row[q]] = aReg[q].x;
        As[0][a_c4[q] * 4 + 1][a_row[q]] = aReg[q].y;
        As[0][a_c4[q] * 4 + 2][a_row[q]] = aReg[q].z;
        As[0][a_c4[q] * 4 + 3][a_row[q]] = aReg[q].w;
    }
    #pragma unroll
    for (int q = 0; q < 2; q++)
        *reinterpret_cast<float4*>(&Ws[0][w_k[q]][w_n4[q]]) = wReg[q];
    __syncthreads();

    ull acc[4][4];
    #pragma unroll
    for (int i = 0; i < 4; i++)
        #pragma unroll
        for (int jj = 0; jj < 4; jj++) acc[i][jj] = 0ull;

    float bv[4];
    #pragma unroll
    for (int jj = 0; jj < 4; jj++) bv[jj] = bias[nGateBase + tx * 4 + jj];

    #pragma unroll 1
    for (int s = 0; s < 8; s++) {
        const int cur = s & 1;
        // issue next chunk's LDGs (hidden under this chunk's FMAs)
        if (s < 7) {
            const int k0 = (s + 1) * 32;
            #pragma unroll
            for (int q = 0; q < 4; q++)
                aReg[q] = *reinterpret_cast<const float4*>(
                    &x[(size_t)(mBase + a_row[q]) * 256 + k0 + a_c4[q] * 4]);
            #pragma unroll
            for (int q = 0; q < 2; q++)
                wReg[q] = *reinterpret_cast<const float4*>(
                    &W[(size_t)(k0 + w_k[q]) * 256 + nGateBase + w_n4[q]]);
        }

        // compute on current buffer
        #pragma unroll
        for (int k = 0; k < 32; k++) {
            const ull* ap = reinterpret_cast<const ull*>(&As[cur][k][ty * 8]);
            ull a0 = ap[0], a1 = ap[1], a2 = ap[2], a3 = ap[3];
            #pragma unroll
            for (int jj = 0; jj < 4; jj++) {
                float w = Ws[cur][k][tx * 4 + jj];
                ull w2 = pack2(w, w);
                fma2(acc[0][jj], a0, w2); fma2(acc[1][jj], a1, w2);
                fma2(acc[2][jj], a2, w2); fma2(acc[3][jj], a3, w2);
            }
        }

        // store next chunk to the alternate buffer (safe: its last readers
        // finished before the sync at the end of iteration s-1)
        if (s < 7) {
            const int nxt = cur ^ 1;
            #pragma unroll
            for (int q = 0; q < 4; q++) {
                As[nxt][a_c4[q] * 4 + 0][a_row[q]] = aReg[q].x;
                As[nxt][a_c4[q] * 4 + 1][a_row[q]] = aReg[q].y;
                As[nxt][a_c4[q] * 4 + 2][a_row[q]] = aReg[q].z;
                As[nxt][a_c4[q] * 4 + 3][a_row[q]] = aReg[q].w;
            }
            #pragma unroll
            for (int q = 0; q < 2; q++)
                *reinterpret_cast<float4*>(&Ws[nxt][w_k[q]][w_n4[q]]) = wReg[q];
            __syncthreads();
        }
    }

    const int nOut = gate * 256 + nGateBase + tx * 4;
    #pragma unroll
    for (int rp = 0; rp < 4; rp++) {
        float r0[4], r1[4];
        #pragma unroll
        for (int jj = 0; jj < 4; jj++) {
            unpack2(acc[rp][jj], r0[jj], r1[jj]);
            r0[jj] += bv[jj]; r1[jj] += bv[jj];
        }
        int m0 = mBase + ty * 8 + rp * 2;
        *reinterpret_cast<float4*>(&g_Gx[(size_t)m0 * 768 + nOut]) =
            make_float4(r0[0], r0[1], r0[2], r0[3]);
        *reinterpret_cast<float4*>(&g_Gx[(size_t)(m0 + 1) * 768 + nOut]) =
            make_float4(r1[0], r1[1], r1[2], r1[3]);
    }
}

// ============================================================================
// Stage 2: recurrence — BYTE-IDENTICAL to R11 (best: rec 2055us).
// 32 clusters x 8 CTAs, 4 rows/cluster, 2 CTAs/SM. Intra-warp split-K with
// shfl butterfly; zero __syncthreads in the loop; split hw cluster barriers.
// ============================================================================
struct __align__(16) RecSmem {
    float wc4[32][8][8][4];    // Wc h-part [kk][c>>2][kg][c&3]          32KB
    float hT[2][264 * 4];      // h, skewed rows of 16B [buf]           8.25KB
    float rhT[264 * 4];        // r*h, skewed                           4.1KB
};

__global__ __launch_bounds__(256, 2) __cluster_dims__(8, 1, 1)
void rec_kernel(const float* __restrict__ h0,
                const float* __restrict__ Wr,
                const float* __restrict__ Wz,
                const float* __restrict__ Wc,
                float* __restrict__ out)
{
    extern __shared__ char smem_raw[];
    RecSmem& S = *reinterpret_cast<RecSmem*>(smem_raw);

    const int tid = threadIdx.x;
    const int warp = tid >> 5, lane = tid & 31;
    const int j = (int)cluster_rank();       // 0..7
    const int b0 = (blockIdx.x >> 3) * 4;    // first batch row of cluster

    // roles
    const int c_local = warp * 4 + (lane & 3);   // output col within CTA, 0..31
    const int kg = lane >> 2;                    // split-K group, 0..7
    const int kb = kg * 32;
    const bool pusher = (lane < 16);
    const int rp = (lane >> 2) & 1;              // row-pair (pushers)
    const int pg = (lane >> 3) & 1;              // peer group (pushers)
    const int k_glob = j * 32 + c_local;
    const int kr_own = k_glob + j;               // skewed row of own col

    // ---- register weights for r and z gates (1 col x 32 k each) ----
    float w1r[32], w1z[32];
    {
        const int c = k_glob;
        #pragma unroll
        for (int kk = 0; kk < 32; kk++) {
            w1r[kk] = Wr[(size_t)(256 + kb + kk) * 256 + c];
            w1z[kk] = Wz[(size_t)(256 + kb + kk) * 256 + c];
        }
    }

    // ---- SMEM init: Wc tile (bank-friendly layout), h state (buffer 0) ----
    for (int idx = tid; idx < 8192; idx += 256) {
        int k = idx >> 5, c = idx & 31;
        S.wc4[k & 31][c >> 2][k >> 5][c & 3] =
            Wc[(size_t)(256 + k) * 256 + j * 32 + c];
    }
    for (int idx = tid; idx < 1024; idx += 256) {
        int k = idx >> 2, r = idx & 3;
        S.hT[0][(k + (k >> 5)) * 4 + r] = h0[(size_t)(b0 + r) * 256 + k];
    }
    __syncthreads();
    cluster_sync();   // peers' hT init visible before any remote op

    // ---- peer DSMEM addresses ----
    const uint32_t base = smem_u32(&S);
    uint32_t peer[8];
    #pragma unroll
    for (int rk = 0; rk < 8; rk++) peer[rk] = mapa_rank(base, (uint32_t)rk);
    const uint32_t off_h[2]  = { (uint32_t)(smem_u32(&S.hT[0][0]) - base),
                                 (uint32_t)(smem_u32(&S.hT[1][0]) - base) };
    const uint32_t off_rh    = (uint32_t)(smem_u32(&S.rhT[0]) - base);

    // ---- Gx address bases for pusher lanes ----
    const size_t bR0 = (size_t)(b0 + 2 * rp)     * TSTEPS * 768 + k_glob;
    const size_t bR1 = (size_t)(b0 + 2 * rp + 1) * TSTEPS * 768 + k_glob;

    // prologue: gR for step 0
    float gR0 = 0.f, gR1 = 0.f;
    if (pusher) { gR0 = g_Gx[bR0]; gR1 = g_Gx[bR1]; }

    #pragma unroll 1
    for (int t = 0; t < TSTEPS; t++) {
        const int buf = t & 1;

        // gZ/gC loads first: latency overlaps WAIT2 + GEMM_r..GEMM_z
        float gZ0 = 0.f, gZ1 = 0.f, gC0 = 0.f, gC1 = 0.f;
        if (pusher) {
            const size_t to = (size_t)t * 768;
            gZ0 = g_Gx[bR0 + to + 256]; gZ1 = g_Gx[bR1 + to + 256];
            gC0 = g_Gx[bR0 + to + 512]; gC1 = g_Gx[bR1 + to + 512];
        }

        // WAIT2: h(t) pushed by all peers at end of step t-1
        if (t > 0) cluster_wait();

        // -- GEMM_r: h @ Wh_r (skewed hT; per-iter row kb+kk+kg) --
        float r0l, r0h, r1l, r1h;
        {
            ull a0 = 0, a1 = 0;
            #pragma unroll
            for (int kk = 0; kk < 32; kk++) {
                ulonglong2 hp = *reinterpret_cast<const ulonglong2*>(
                    &S.hT[buf][(kb + kk + kg) * 4]);
                ull w2 = pack2(w1r[kk], w1r[kk]);
                fma2(a0, hp.x, w2); fma2(a1, hp.y, w2);
            }
            unpack2(a0, r0l, r0h); unpack2(a1, r1l, r1h);
            bfly_kg(r0l, r0h); bfly_kg(r1l, r1h);
        }

        // -- epi_r (pushers): sigmoid r, push r*h (4 peers each) --
        if (pusher) {
            float sl = rp ? r1l : r0l, sh = rp ? r1h : r0h;
            float v0 = fast_sigmoid(sl + gR0), v1 = fast_sigmoid(sh + gR1);
            ull h2 = *reinterpret_cast<const ull*>(&S.hT[buf][kr_own * 4 + 2 * rp]);
            float ha, hb; unpack2(h2, ha, hb);
            ull rh2 = pack2(v0 * ha, v1 * hb);
            uint32_t o = off_rh + (uint32_t)((kr_own * 4 + 2 * rp) * 4);
            #pragma unroll
            for (int p = 0; p < 4; p++) st_cluster_u64(peer[4 * pg + p] + o, rh2);
        }
        // ARRIVE1: rh pushes issued (release); propagation hides under GEMM_z
        cluster_arrive();

        // -- GEMM_z: h @ Wh_z (overlaps the r*h exchange + barrier) --
        float z0 = 0.f, z1 = 0.f;
        {
            ull a0 = 0, a1 = 0;
            #pragma unroll
            for (int kk = 0; kk < 32; kk++) {
                ulonglong2 hp = *reinterpret_cast<const ulonglong2*>(
                    &S.hT[buf][(kb + kk + kg) * 4]);
                ull w2 = pack2(w1z[kk], w1z[kk]);
                fma2(a0, hp.x, w2); fma2(a1, hp.y, w2);
            }
            float z0l, z0h, z1l, z1h;
            unpack2(a0, z0l, z0h); unpack2(a1, z1l, z1h);
            bfly_kg(z0l, z0h); bfly_kg(z1l, z1h);
            if (pusher) {   // z stays in registers until epi_c (same lane)
                float sl = rp ? z1l : z0l, sh = rp ? z1h : z0h;
                z0 = fast_sigmoid(sl + gZ0); z1 = fast_sigmoid(sh + gZ1);
            }
        }

        // issue gR(t+1) prefetch BEFORE the wait: in flight across WAIT1+GEMM_c
        float gRn0 = gR0, gRn1 = gR1;
        if (pusher) {
            const size_t tn = (size_t)((t + 1 < TSTEPS) ? t + 1 : t) * 768;
            gRn0 = g_Gx[bR0 + tn]; gRn1 = g_Gx[bR1 + tn];
        }

        // WAIT1: rhT complete from all peers (mostly satisfied already)
        cluster_wait();

        // -- GEMM_c: (r*h) @ Wh_c (Wc from bank-friendly SMEM) --
        float c0l, c0h, c1l, c1h;
        {
            ull a0 = 0, a1 = 0;
            #pragma unroll
            for (int kk = 0; kk < 32; kk++) {
                ulonglong2 hp = *reinterpret_cast<const ulonglong2*>(
                    &S.rhT[(kb + kk + kg) * 4]);
                float w = S.wc4[kk][c_local >> 2][kg][c_local & 3];
                ull w2 = pack2(w, w);
                fma2(a0, hp.x, w2); fma2(a1, hp.y, w2);
            }
            unpack2(a0, c0l, c0h); unpack2(a1, c1l, c1h);
            bfly_kg(c0l, c0h); bfly_kg(c1l, c1h);
        }

        // -- epi_c (pushers): candidate, h update, output, push h(t+1) --
        if (pusher) {
            float sl = rp ? c1l : c0l, sh = rp ? c1h : c0h;
            float cv0 = fast_tanh(sl + gC0), cv1 = fast_tanh(sh + gC1);
            ull h2 = *reinterpret_cast<const ull*>(&S.hT[buf][kr_own * 4 + 2 * rp]);
            float ha, hb; unpack2(h2, ha, hb);
            float hn0 = ha + z0 * (cv0 - ha);
            float hn1 = hb + z1 * (cv1 - hb);
            if (pg == 0) {
                out[((size_t)(b0 + 2 * rp) * TSTEPS + t) * 256 + k_glob] = hn0;
                out[((size_t)(b0 + 2 * rp + 1) * TSTEPS + t) * 256 + k_glob] = hn1;
            }
            ull hn2 = pack2(hn0, hn1);
            uint32_t o = off_h[buf ^ 1] + (uint32_t)((kr_own * 4 + 2 * rp) * 4);
            #pragma unroll
            for (int p = 0; p < 4; p++) st_cluster_u64(peer[4 * pg + p] + o, hn2);
        }
        // ARRIVE2: h(t+1) pushes issued; next iteration's wait consumes it
        cluster_arrive();

        gR0 = gRn0; gR1 = gRn1;
    }

    // consume the final ARRIVE2 so no CTA exits with peer pushes in flight
    cluster_wait();
}

extern "C" void kernel_launch(void* const* d_in, const int* in_sizes, int n_in,
                              void* d_out, int out_size) {
    const float* x  = (const float*)d_in[0];
    const float* h0 = (const float*)d_in[1];
    const float* Wr = (const float*)d_in[2];
    const float* br = (const float*)d_in[3];
    const float* Wz = (const float*)d_in[4];
    const float* bz = (const float*)d_in[5];
    const float* Wc = (const float*)d_in[6];
    const float* bc = (const float*)d_in[7];
    float* out = (float*)d_out;

    const int proj_smem = PROJ_SMEM_FLOATS * (int)sizeof(float);
    cudaFuncSetAttribute(proj_kernel, cudaFuncAttributeMaxDynamicSharedMemorySize,
                         proj_smem);
    cudaFuncSetAttribute(rec_kernel, cudaFuncAttributeMaxDynamicSharedMemorySize,
                         (int)sizeof(RecSmem));

    proj_kernel<<<dim3(512, 12), 256, proj_smem>>>(x, Wr, br, Wz, bz, Wc, bc);
    rec_kernel<<<256, 256, sizeof(RecSmem)>>>(h0, Wr, Wz, Wc, out);
}